// round 13
// baseline (speedup 1.0000x reference)
#include <cuda_runtime.h>
#include <cuda.h>
#include <cuda_fp16.h>

// HashGrid1D on GB300 — R13 (= verified R9 + next-x prefetch + paired lvl9).
// Tables: levels 0..8 pair-packed half4 in smem (65.5KB), level 9 pair-packed
// half4 in smem (65.5KB), levels 10+11 fused single L2 gather (g_comb,
// indexed by unhashed i11). Store: SW128-swizzled STS.128 -> TMA 2D store.
// Loop shape identical to R9; only the next iteration's raw x value is
// prefetched (1 carried register) so the iteration-top gather never waits
// on a fresh DRAM load.

#define HASH_MASK 16383
#define COMB_N    32769
#define SMEM_PAIRS 8185             // sum_{l=0}^{8} ((16<<l)+1)
#define L9_PAIRS   8193             // level 9 pair entries i=0..8192
#define L9_ENTRIES 8194
#define TBL_SCALE     16384.0f
#define TBL_INV_SCALE 6.103515625e-05f  // exact 2^-14

#define PAIR_BYTES  65488           // 8185*8 padded to 16
#define L9P_BYTES   65552           // 8193*8 padded to 16
#define STAGE_BYTES (32 * 3072)     // 32 warps x 3KB
#define SMEM_TMA    (1024 + STAGE_BYTES + PAIR_BYTES + L9P_BYTES)  // 230368 (fits; ran in R10)

// fallback: unpaired lvl9 + stride-7 fp32 staging (R7-proven)
#define L9U_BYTES    32784
#define FB_TBL       (PAIR_BYTES + L9U_BYTES)
#define SMEM_FB      (FB_TBL + 1024 * 7 * 16)   // 212960

__device__ uint4 g_comb[COMB_N];

__device__ __forceinline__ unsigned pack_h2(float2 a)
{
    __half2 h = __floats2half2_rn(a.x * TBL_SCALE, a.y * TBL_SCALE);
    return *reinterpret_cast<unsigned*>(&h);
}

__device__ __forceinline__ float2 lerp_h2pair(unsigned u0, unsigned u1, float w)
{
    float2 e0 = __half22float2(*reinterpret_cast<__half2*>(&u0));
    float2 e1 = __half22float2(*reinterpret_cast<__half2*>(&u1));
    float2 r;
    r.x = fmaf(w, e1.x - e0.x, e0.x) * TBL_INV_SCALE;
    r.y = fmaf(w, e1.y - e0.y, e0.y) * TBL_INV_SCALE;
    return r;
}

__global__ void build_comb_kernel(const float* __restrict__ table)
{
    int j = blockIdx.x * blockDim.x + threadIdx.x;
    if (j >= COMB_N) return;
    int i10 = j >> 1;
    uint4 v;
    v.x = pack_h2(*reinterpret_cast<const float2*>(table + (i10 & HASH_MASK)       * 24 + 20));
    v.y = pack_h2(*reinterpret_cast<const float2*>(table + ((i10 + 1) & HASH_MASK) * 24 + 20));
    v.z = pack_h2(*reinterpret_cast<const float2*>(table + (j & HASH_MASK)         * 24 + 22));
    v.w = pack_h2(*reinterpret_cast<const float2*>(table + ((j + 1) & HASH_MASK)   * 24 + 22));
    g_comb[j] = v;
}

__device__ __forceinline__ void fill_spair(const float* __restrict__ table, uint2* spair)
{
    const int off[10] = {0, 17, 50, 115, 244, 501, 1014, 2039, 4088, 8185};
    for (int e = threadIdx.x; e < SMEM_PAIRS; e += blockDim.x) {
        int l = 0;
        #pragma unroll
        for (int k = 1; k < 9; ++k) l += (e >= off[k]);
        int i = e - off[l];
        uint2 v;
        v.x = pack_h2(*reinterpret_cast<const float2*>(table + i       * 24 + 2 * l));
        v.y = pack_h2(*reinterpret_cast<const float2*>(table + (i + 1) * 24 + 2 * l));
        spair[e] = v;
    }
}

// levels 0..8 (pairs) + level 9 (pairs) + levels 10/11 (prefetched g)
__device__ __forceinline__ void compute_point(float xc, const uint2* spair,
                                              const uint2* s9p, uint4 g, float* of)
{
    const int off[10] = {0, 17, 50, 115, 244, 501, 1014, 2039, 4088, 8185};
    float res = 16.0f;
    #pragma unroll
    for (int l = 0; l < 9; ++l) {
        float pos = xc * res;
        int   i0  = __float2int_rd(pos);
        float w   = pos - (float)i0;
        uint2 v   = spair[off[l] + i0];
        float2 r  = lerp_h2pair(v.x, v.y, w);
        of[2 * l]     = r.x;
        of[2 * l + 1] = r.y;
        res *= 2.0f;
    }
    {
        float pos = xc * 8192.0f;
        int   i0  = __float2int_rd(pos);
        float w   = pos - (float)i0;
        uint2 v   = s9p[i0];
        float2 r  = lerp_h2pair(v.x, v.y, w);
        of[18] = r.x; of[19] = r.y;
    }
    {
        float pos11 = xc * 32768.0f;
        int   i11   = __float2int_rd(pos11);
        float w11   = pos11 - (float)i11;
        int   i10   = i11 >> 1;
        float w10   = pos11 * 0.5f - (float)i10;
        float2 r = lerp_h2pair(g.x, g.y, w10);
        of[20] = r.x; of[21] = r.y;
        r = lerp_h2pair(g.z, g.w, w11);
        of[22] = r.x; of[23] = r.y;
    }
}

// ---------------- TMA kernel ----------------
__global__ void __launch_bounds__(1024, 1)
hashgrid1d_tma_kernel(const float* __restrict__ x,
                      const float* __restrict__ table,
                      float* __restrict__ out, int n,
                      const __grid_constant__ CUtensorMap tmap)
{
    extern __shared__ unsigned char smem_raw[];
    unsigned sbase_s = (unsigned)__cvta_generic_to_shared(smem_raw);
    unsigned pad     = ((sbase_s + 1023u) & ~1023u) - sbase_s;
    unsigned char* stage_g = smem_raw + pad;
    unsigned stage_s = sbase_s + pad;
    uint2* spair = reinterpret_cast<uint2*>(stage_g + STAGE_BYTES);
    uint2* s9p   = reinterpret_cast<uint2*>(stage_g + STAGE_BYTES + PAIR_BYTES);

    fill_spair(table, spair);
    for (int i = threadIdx.x; i < L9_PAIRS; i += blockDim.x) {
        uint2 v;
        v.x = pack_h2(*reinterpret_cast<const float2*>(table + i       * 24 + 18));
        v.y = pack_h2(*reinterpret_cast<const float2*>(table + (i + 1) * 24 + 18));
        s9p[i] = v;
    }
    __syncthreads();

    const int lane = threadIdx.x & 31;
    const int wid  = threadIdx.x >> 5;
    float4*  my_stage   = reinterpret_cast<float4*>(stage_g + wid * 3072);
    unsigned my_stage_s = stage_s + wid * 3072;

    int gwarp  = (blockIdx.x * blockDim.x + threadIdx.x) >> 5;
    int nwarps = (gridDim.x * blockDim.x) >> 5;
    int step   = nwarps * 32;
    int nfull  = n & ~31;

    int b0 = gwarp * 32;
    float xraw = (b0 < nfull) ? x[b0 + lane] : 0.0f;   // prologue x

    for (; b0 < nfull; b0 += step) {
        float xc = fminf(fmaxf(xraw, 0.0f), 1.0f);
        uint4 g  = __ldg(&g_comb[__float2int_rd(xc * 32768.0f)]);

        // prefetch next iteration's raw x (independent; lands during compute)
        int bn = b0 + step;
        if (bn < nfull) xraw = x[bn + lane];

        float4 o[6];
        compute_point(xc, spair, s9p, g, reinterpret_cast<float*>(o));

        if (lane == 0)
            asm volatile("cp.async.bulk.wait_group.read 0;" ::: "memory");
        __syncwarp();

        // SW128-swizzled conflict-free STS.128
        #pragma unroll
        for (int j = 0; j < 6; ++j) {
            unsigned u = 6u * lane + j;
            unsigned s = u ^ ((u >> 3) & 7u);
            my_stage[s] = o[j];
        }
        __syncwarp();

        if (lane == 0) {
            asm volatile("fence.proxy.async.shared::cta;" ::: "memory");
            int row0 = (b0 >> 5) * 24;
            asm volatile(
                "cp.async.bulk.tensor.2d.global.shared::cta.tile.bulk_group "
                "[%0, {%1, %2}], [%3];"
                :: "l"(&tmap), "r"(0), "r"(row0), "r"(my_stage_s) : "memory");
            asm volatile("cp.async.bulk.commit_group;" ::: "memory");
        }
    }
    asm volatile("cp.async.bulk.wait_group 0;" ::: "memory");

    // tail (n not multiple of 32): guarded direct stores
    for (int b = nfull + gwarp * 32 + lane; b < n; b += step) {
        float xc = fminf(fmaxf(x[b], 0.0f), 1.0f);
        uint4 g  = __ldg(&g_comb[__float2int_rd(xc * 32768.0f)]);
        float4 o[6];
        compute_point(xc, spair, s9p, g, reinterpret_cast<float*>(o));
        float4* op = reinterpret_cast<float4*>(out + (size_t)b * 24);
        #pragma unroll
        for (int j = 0; j < 6; ++j) op[j] = o[j];
    }
}

// ---------------- fallback: smem transpose + coalesced STG (R7-proven) ----------------
__global__ void __launch_bounds__(1024, 1)
hashgrid1d_fb_kernel(const float* __restrict__ x,
                     const float* __restrict__ table,
                     float* __restrict__ out, int n)
{
    extern __shared__ unsigned char smem_raw[];
    uint2*    spair = reinterpret_cast<uint2*>(smem_raw);
    unsigned* s9    = reinterpret_cast<unsigned*>(smem_raw + PAIR_BYTES);
    float4*   stage = reinterpret_cast<float4*>(smem_raw + FB_TBL);

    fill_spair(table, spair);
    for (int i = threadIdx.x; i < L9_ENTRIES; i += blockDim.x)
        s9[i] = pack_h2(*reinterpret_cast<const float2*>(table + i * 24 + 18));
    __syncthreads();

    const int lane = threadIdx.x & 31;
    float4* my_stage = stage + (threadIdx.x >> 5) * 224;

    int stride = gridDim.x * blockDim.x;
    for (int b = blockIdx.x * blockDim.x + threadIdx.x; b < n; b += stride) {
        float xc = fminf(fmaxf(x[b], 0.0f), 1.0f);
        uint4 g  = __ldg(&g_comb[__float2int_rd(xc * 32768.0f)]);
        float4 o[6];
        float* of = reinterpret_cast<float*>(o);
        {
            const int off[10] = {0, 17, 50, 115, 244, 501, 1014, 2039, 4088, 8185};
            float res = 16.0f;
            #pragma unroll
            for (int l = 0; l < 9; ++l) {
                float pos = xc * res;
                int   i0  = __float2int_rd(pos);
                float w   = pos - (float)i0;
                uint2 v   = spair[off[l] + i0];
                float2 r  = lerp_h2pair(v.x, v.y, w);
                of[2 * l] = r.x; of[2 * l + 1] = r.y;
                res *= 2.0f;
            }
            float pos = xc * 8192.0f;
            int   i0  = __float2int_rd(pos);
            float w   = pos - (float)i0;
            float2 r  = lerp_h2pair(s9[i0], s9[i0 + 1], w);
            of[18] = r.x; of[19] = r.y;
        }
        {
            float pos11 = xc * 32768.0f;
            int   i11   = __float2int_rd(pos11);
            float w11   = pos11 - (float)i11;
            int   i10   = i11 >> 1;
            float w10   = pos11 * 0.5f - (float)i10;
            float2 r = lerp_h2pair(g.x, g.y, w10);
            of[20] = r.x; of[21] = r.y;
            r = lerp_h2pair(g.z, g.w, w11);
            of[22] = r.x; of[23] = r.y;
        }

        #pragma unroll
        for (int j = 0; j < 6; ++j) my_stage[lane * 7 + j] = o[j];
        __syncwarp();
        float4* ob = reinterpret_cast<float4*>(out + (size_t)(b - lane) * 24);
        #pragma unroll
        for (int k = 0; k < 6; ++k) {
            int w4 = lane + 32 * k;
            int p  = (w4 * 2731) >> 14;
            int c  = w4 - p * 6;
            ob[w4] = my_stage[p * 7 + c];
        }
        __syncwarp();
    }
}

extern "C" void kernel_launch(void* const* d_in, const int* in_sizes, int n_in,
                              void* d_out, int out_size)
{
    const float* x     = (const float*)d_in[0];
    const float* table = (const float*)d_in[1];
    float*       out   = (float*)d_out;
    int n = in_sizes[0];
    int nfull = n & ~31;

    int sm_count = 148;
    cudaDeviceGetAttribute(&sm_count, cudaDevAttrMultiProcessorCount, 0);

    bool use_tma = false;
    CUtensorMap tmap;
    void* sym = nullptr;
    cudaDriverEntryPointQueryResult qres;
#if CUDART_VERSION >= 12050
    if (cudaGetDriverEntryPointByVersion("cuTensorMapEncodeTiled", &sym, 12000,
                                         cudaEnableDefault, &qres) != cudaSuccess)
        sym = nullptr;
#else
    if (cudaGetDriverEntryPoint("cuTensorMapEncodeTiled", &sym,
                                cudaEnableDefault, &qres) != cudaSuccess)
        sym = nullptr;
#endif
    if (sym && nfull > 0) {
        typedef CUresult (*Enc)(CUtensorMap*, CUtensorMapDataType, cuuint32_t, void*,
                                const cuuint64_t*, const cuuint64_t*,
                                const cuuint32_t*, const cuuint32_t*,
                                CUtensorMapInterleave, CUtensorMapSwizzle,
                                CUtensorMapL2promotion, CUtensorMapFloatOOBfill);
        Enc enc = (Enc)sym;
        cuuint64_t dims[2]    = {32ull, (cuuint64_t)(nfull / 32) * 24ull};
        cuuint64_t strides[1] = {128ull};
        cuuint32_t box[2]     = {32u, 24u};
        cuuint32_t estr[2]    = {1u, 1u};
        if (enc(&tmap, CU_TENSOR_MAP_DATA_TYPE_FLOAT32, 2, out,
                dims, strides, box, estr,
                CU_TENSOR_MAP_INTERLEAVE_NONE, CU_TENSOR_MAP_SWIZZLE_128B,
                CU_TENSOR_MAP_L2_PROMOTION_L2_128B,
                CU_TENSOR_MAP_FLOAT_OOB_FILL_NONE) == CUDA_SUCCESS)
            use_tma = true;
    }
    if (use_tma &&
        cudaFuncSetAttribute(hashgrid1d_tma_kernel,
                             cudaFuncAttributeMaxDynamicSharedMemorySize,
                             SMEM_TMA) != cudaSuccess)
        use_tma = false;

    build_comb_kernel<<<(COMB_N + 255) / 256, 256>>>(table);

    if (use_tma) {
        hashgrid1d_tma_kernel<<<sm_count, 1024, SMEM_TMA>>>(x, table, out, n, tmap);
    } else {
        cudaFuncSetAttribute(hashgrid1d_fb_kernel,
                             cudaFuncAttributeMaxDynamicSharedMemorySize, SMEM_FB);
        hashgrid1d_fb_kernel<<<sm_count, 1024, SMEM_FB>>>(x, table, out, n);
    }
}

// round 14
// speedup vs baseline: 1.0561x; 1.0561x over previous
#include <cuda_runtime.h>
#include <cuda.h>
#include <cuda_fp16.h>

// HashGrid1D on GB300 — R14 (= verified R9 + next-x prefetch ONLY).
// Finding from R10..R13: kernel time tracks smem footprint (L1D carveout =
// 228KB - smem). R9's 197.6KB leaves ~30KB L1D that caches x + part of the
// gather table; exceeding it cost 8-14us. So smem layout stays EXACTLY R9:
// levels 0..8 pair-packed half4 (65.5KB) + level 9 unpaired half2 (32.8KB)
// + 96KB staging. Only change: prefetch next iteration's raw x (1 register).

#define HASH_MASK 16383
#define COMB_N    32769
#define SMEM_PAIRS 8185             // sum_{l=0}^{8} ((16<<l)+1)
#define L9_ENTRIES 8194
#define TBL_SCALE     16384.0f
#define TBL_INV_SCALE 6.103515625e-05f  // exact 2^-14
#define PAIR_BYTES  65488           // 8185*8 padded to 16
#define L9_BYTES    32784           // 8194*4 padded to 16
#define TBL_BYTES   (PAIR_BYTES + L9_BYTES)          // 98272
#define STAGE_BYTES (32 * 3072)                       // 98304
#define SMEM_TMA    (1024 + STAGE_BYTES + TBL_BYTES)  // 197600
#define SMEM_FB     (TBL_BYTES + 1024 * 7 * 16)       // 212960

__device__ uint4 g_comb[COMB_N];   // {h2 e10[i10h], h2 e10[i10h+1], h2 e11[i11h], h2 e11[i11h+1]}

__device__ __forceinline__ unsigned pack_h2(float2 a)
{
    __half2 h = __floats2half2_rn(a.x * TBL_SCALE, a.y * TBL_SCALE);
    return *reinterpret_cast<unsigned*>(&h);
}

__device__ __forceinline__ float2 lerp_h2pair(unsigned u0, unsigned u1, float w)
{
    float2 e0 = __half22float2(*reinterpret_cast<__half2*>(&u0));
    float2 e1 = __half22float2(*reinterpret_cast<__half2*>(&u1));
    float2 r;
    r.x = fmaf(w, e1.x - e0.x, e0.x) * TBL_INV_SCALE;
    r.y = fmaf(w, e1.y - e0.y, e0.y) * TBL_INV_SCALE;
    return r;
}

__global__ void build_comb_kernel(const float* __restrict__ table)
{
    int j = blockIdx.x * blockDim.x + threadIdx.x;
    if (j >= COMB_N) return;
    int i10 = j >> 1;
    uint4 v;
    v.x = pack_h2(*reinterpret_cast<const float2*>(table + (i10 & HASH_MASK)       * 24 + 20));
    v.y = pack_h2(*reinterpret_cast<const float2*>(table + ((i10 + 1) & HASH_MASK) * 24 + 20));
    v.z = pack_h2(*reinterpret_cast<const float2*>(table + (j & HASH_MASK)         * 24 + 22));
    v.w = pack_h2(*reinterpret_cast<const float2*>(table + ((j + 1) & HASH_MASK)   * 24 + 22));
    g_comb[j] = v;
}

__device__ __forceinline__ void fill_tables(const float* __restrict__ table,
                                            uint2* spair, unsigned* s9)
{
    const int off[10] = {0, 17, 50, 115, 244, 501, 1014, 2039, 4088, 8185};
    for (int e = threadIdx.x; e < SMEM_PAIRS; e += blockDim.x) {
        int l = 0;
        #pragma unroll
        for (int k = 1; k < 9; ++k) l += (e >= off[k]);
        int i = e - off[l];
        uint2 v;
        v.x = pack_h2(*reinterpret_cast<const float2*>(table + i       * 24 + 2 * l));
        v.y = pack_h2(*reinterpret_cast<const float2*>(table + (i + 1) * 24 + 2 * l));
        spair[e] = v;
    }
    for (int i = threadIdx.x; i < L9_ENTRIES; i += blockDim.x)
        s9[i] = pack_h2(*reinterpret_cast<const float2*>(table + i * 24 + 18));
}

__device__ __forceinline__ void compute_point(float xc, const uint2* spair,
                                              const unsigned* s9, uint4 g, float* of)
{
    const int off[10] = {0, 17, 50, 115, 244, 501, 1014, 2039, 4088, 8185};
    float res = 16.0f;
    #pragma unroll
    for (int l = 0; l < 9; ++l) {
        float pos = xc * res;
        int   i0  = __float2int_rd(pos);
        float w   = pos - (float)i0;
        uint2 v   = spair[off[l] + i0];
        float2 r  = lerp_h2pair(v.x, v.y, w);
        of[2 * l]     = r.x;
        of[2 * l + 1] = r.y;
        res *= 2.0f;
    }
    {
        float pos = xc * 8192.0f;
        int   i0  = __float2int_rd(pos);
        float w   = pos - (float)i0;
        float2 r  = lerp_h2pair(s9[i0], s9[i0 + 1], w);
        of[18] = r.x; of[19] = r.y;
    }
    {
        float pos11 = xc * 32768.0f;
        int   i11   = __float2int_rd(pos11);
        float w11   = pos11 - (float)i11;
        int   i10   = i11 >> 1;
        float w10   = pos11 * 0.5f - (float)i10;
        float2 r = lerp_h2pair(g.x, g.y, w10);
        of[20] = r.x; of[21] = r.y;
        r = lerp_h2pair(g.z, g.w, w11);
        of[22] = r.x; of[23] = r.y;
    }
}

// ---------------- TMA kernel ----------------
__global__ void __launch_bounds__(1024, 1)
hashgrid1d_tma_kernel(const float* __restrict__ x,
                      const float* __restrict__ table,
                      float* __restrict__ out, int n,
                      const __grid_constant__ CUtensorMap tmap)
{
    extern __shared__ unsigned char smem_raw[];
    unsigned sbase_s = (unsigned)__cvta_generic_to_shared(smem_raw);
    unsigned pad     = ((sbase_s + 1023u) & ~1023u) - sbase_s;
    unsigned char* stage_g = smem_raw + pad;
    unsigned stage_s = sbase_s + pad;
    uint2*    spair = reinterpret_cast<uint2*>(stage_g + STAGE_BYTES);
    unsigned* s9    = reinterpret_cast<unsigned*>(stage_g + STAGE_BYTES + PAIR_BYTES);

    fill_tables(table, spair, s9);
    __syncthreads();

    const int lane = threadIdx.x & 31;
    const int wid  = threadIdx.x >> 5;
    float4*  my_stage   = reinterpret_cast<float4*>(stage_g + wid * 3072);
    unsigned my_stage_s = stage_s + wid * 3072;

    int gwarp  = (blockIdx.x * blockDim.x + threadIdx.x) >> 5;
    int nwarps = (gridDim.x * blockDim.x) >> 5;
    int step   = nwarps * 32;
    int nfull  = n & ~31;

    int b0 = gwarp * 32;
    float xraw = (b0 < nfull) ? x[b0 + lane] : 0.0f;   // prologue x

    for (; b0 < nfull; b0 += step) {
        float xc = fminf(fmaxf(xraw, 0.0f), 1.0f);
        uint4 g  = __ldg(&g_comb[__float2int_rd(xc * 32768.0f)]);

        // prefetch next iteration's raw x (independent of everything below)
        int bn = b0 + step;
        if (bn < nfull) xraw = x[bn + lane];

        float4 o[6];
        compute_point(xc, spair, s9, g, reinterpret_cast<float*>(o));

        if (lane == 0)
            asm volatile("cp.async.bulk.wait_group.read 0;" ::: "memory");
        __syncwarp();

        // SW128-swizzled conflict-free STS.128
        #pragma unroll
        for (int j = 0; j < 6; ++j) {
            unsigned u = 6u * lane + j;
            unsigned s = u ^ ((u >> 3) & 7u);
            my_stage[s] = o[j];
        }
        __syncwarp();

        if (lane == 0) {
            asm volatile("fence.proxy.async.shared::cta;" ::: "memory");
            int row0 = (b0 >> 5) * 24;
            asm volatile(
                "cp.async.bulk.tensor.2d.global.shared::cta.tile.bulk_group "
                "[%0, {%1, %2}], [%3];"
                :: "l"(&tmap), "r"(0), "r"(row0), "r"(my_stage_s) : "memory");
            asm volatile("cp.async.bulk.commit_group;" ::: "memory");
        }
    }
    asm volatile("cp.async.bulk.wait_group 0;" ::: "memory");

    // tail (n not multiple of 32): guarded direct stores
    for (int b = nfull + gwarp * 32 + lane; b < n; b += step) {
        float xc = fminf(fmaxf(x[b], 0.0f), 1.0f);
        uint4 g  = __ldg(&g_comb[__float2int_rd(xc * 32768.0f)]);
        float4 o[6];
        compute_point(xc, spair, s9, g, reinterpret_cast<float*>(o));
        float4* op = reinterpret_cast<float4*>(out + (size_t)b * 24);
        #pragma unroll
        for (int j = 0; j < 6; ++j) op[j] = o[j];
    }
}

// ---------------- fallback: smem transpose + coalesced STG ----------------
__global__ void __launch_bounds__(1024, 1)
hashgrid1d_fb_kernel(const float* __restrict__ x,
                     const float* __restrict__ table,
                     float* __restrict__ out, int n)
{
    extern __shared__ unsigned char smem_raw[];
    uint2*    spair = reinterpret_cast<uint2*>(smem_raw);
    unsigned* s9    = reinterpret_cast<unsigned*>(smem_raw + PAIR_BYTES);
    float4*   stage = reinterpret_cast<float4*>(smem_raw + TBL_BYTES);

    fill_tables(table, spair, s9);
    __syncthreads();

    const int lane = threadIdx.x & 31;
    float4* my_stage = stage + (threadIdx.x >> 5) * 224;

    int stride = gridDim.x * blockDim.x;
    for (int b = blockIdx.x * blockDim.x + threadIdx.x; b < n; b += stride) {
        float xc = fminf(fmaxf(x[b], 0.0f), 1.0f);
        uint4 g  = __ldg(&g_comb[__float2int_rd(xc * 32768.0f)]);
        float4 o[6];
        compute_point(xc, spair, s9, g, reinterpret_cast<float*>(o));

        #pragma unroll
        for (int j = 0; j < 6; ++j) my_stage[lane * 7 + j] = o[j];
        __syncwarp();
        float4* ob = reinterpret_cast<float4*>(out + (size_t)(b - lane) * 24);
        #pragma unroll
        for (int k = 0; k < 6; ++k) {
            int w4 = lane + 32 * k;
            int p  = (w4 * 2731) >> 14;
            int c  = w4 - p * 6;
            ob[w4] = my_stage[p * 7 + c];
        }
        __syncwarp();
    }
}

extern "C" void kernel_launch(void* const* d_in, const int* in_sizes, int n_in,
                              void* d_out, int out_size)
{
    const float* x     = (const float*)d_in[0];
    const float* table = (const float*)d_in[1];
    float*       out   = (float*)d_out;
    int n = in_sizes[0];
    int nfull = n & ~31;

    int sm_count = 148;
    cudaDeviceGetAttribute(&sm_count, cudaDevAttrMultiProcessorCount, 0);

    bool use_tma = false;
    CUtensorMap tmap;
    void* sym = nullptr;
    cudaDriverEntryPointQueryResult qres;
#if CUDART_VERSION >= 12050
    if (cudaGetDriverEntryPointByVersion("cuTensorMapEncodeTiled", &sym, 12000,
                                         cudaEnableDefault, &qres) != cudaSuccess)
        sym = nullptr;
#else
    if (cudaGetDriverEntryPoint("cuTensorMapEncodeTiled", &sym,
                                cudaEnableDefault, &qres) != cudaSuccess)
        sym = nullptr;
#endif
    if (sym && nfull > 0) {
        typedef CUresult (*Enc)(CUtensorMap*, CUtensorMapDataType, cuuint32_t, void*,
                                const cuuint64_t*, const cuuint64_t*,
                                const cuuint32_t*, const cuuint32_t*,
                                CUtensorMapInterleave, CUtensorMapSwizzle,
                                CUtensorMapL2promotion, CUtensorMapFloatOOBfill);
        Enc enc = (Enc)sym;
        cuuint64_t dims[2]    = {32ull, (cuuint64_t)(nfull / 32) * 24ull};
        cuuint64_t strides[1] = {128ull};
        cuuint32_t box[2]     = {32u, 24u};
        cuuint32_t estr[2]    = {1u, 1u};
        if (enc(&tmap, CU_TENSOR_MAP_DATA_TYPE_FLOAT32, 2, out,
                dims, strides, box, estr,
                CU_TENSOR_MAP_INTERLEAVE_NONE, CU_TENSOR_MAP_SWIZZLE_128B,
                CU_TENSOR_MAP_L2_PROMOTION_L2_128B,
                CU_TENSOR_MAP_FLOAT_OOB_FILL_NONE) == CUDA_SUCCESS)
            use_tma = true;
    }
    if (use_tma &&
        cudaFuncSetAttribute(hashgrid1d_tma_kernel,
                             cudaFuncAttributeMaxDynamicSharedMemorySize,
                             SMEM_TMA) != cudaSuccess)
        use_tma = false;

    build_comb_kernel<<<(COMB_N + 255) / 256, 256>>>(table);

    if (use_tma) {
        hashgrid1d_tma_kernel<<<sm_count, 1024, SMEM_TMA>>>(x, table, out, n, tmap);
    } else {
        cudaFuncSetAttribute(hashgrid1d_fb_kernel,
                             cudaFuncAttributeMaxDynamicSharedMemorySize, SMEM_FB);
        hashgrid1d_fb_kernel<<<sm_count, 1024, SMEM_FB>>>(x, table, out, n);
    }
}

// round 15
// speedup vs baseline: 1.1286x; 1.0686x over previous
#include <cuda_runtime.h>
#include <cuda.h>
#include <cuda_fp16.h>

// HashGrid1D on GB300 — FINAL (= R9, verified 88.9us; best of 14 rounds).
// Design:
//  - Levels 0..8: pair-packed half4 tables in smem (65.5KB) -> 1 LDS.64/level.
//  - Level 9: unpaired half2 in smem (32.8KB) -> 2 LDS.32.
//  - Levels 10+11: ONE fused L2-resident gather (g_comb, 524KB) indexed by
//    UNHASHED i11 (i10 = i11>>1 exactly); entry holds both levels' lerp pairs.
//  - Table values scaled by 2^14 into half's sweet spot; undone by exact 2^-14.
//  - Output: each warp stages its 32 points (3KB) via SW128-swizzled
//    conflict-free STS.128, then one lane issues cp.async.bulk.tensor.2d
//    (TMA de-swizzles to linear gmem). No LDS readback, no STG wavefronts.
//  - smem total 197.6KB: leaves ~30KB L1D carveout (measured: going above
//    this costs 8-14us — R10/R11/R13 all regressed on footprint alone).
// Failed variants (keep for the record): software pipelining (R10),
// LDS.128 level-pair fusion (R11), 64-pt tiles (R12), x-prefetch (R13/R14).

#define HASH_MASK 16383
#define COMB_N    32769
#define SMEM_PAIRS 8185             // sum_{l=0}^{8} ((16<<l)+1)
#define L9_ENTRIES 8194
#define TBL_SCALE     16384.0f
#define TBL_INV_SCALE 6.103515625e-05f  // exact 2^-14
#define PAIR_BYTES  65488           // 8185*8 padded to 16
#define L9_BYTES    32784           // 8194*4 padded to 16
#define TBL_BYTES   (PAIR_BYTES + L9_BYTES)          // 98272
#define STAGE_BYTES (32 * 3072)                       // 98304
#define SMEM_TMA    (1024 + STAGE_BYTES + TBL_BYTES)  // 197600
#define SMEM_FB     (TBL_BYTES + 1024 * 7 * 16)       // 212960

__device__ uint4 g_comb[COMB_N];   // {h2 e10[i10h], h2 e10[i10h+1], h2 e11[i11h], h2 e11[i11h+1]}

__device__ __forceinline__ unsigned pack_h2(float2 a)
{
    __half2 h = __floats2half2_rn(a.x * TBL_SCALE, a.y * TBL_SCALE);
    return *reinterpret_cast<unsigned*>(&h);
}

__device__ __forceinline__ float2 lerp_h2pair(unsigned u0, unsigned u1, float w)
{
    float2 e0 = __half22float2(*reinterpret_cast<__half2*>(&u0));
    float2 e1 = __half22float2(*reinterpret_cast<__half2*>(&u1));
    float2 r;
    r.x = fmaf(w, e1.x - e0.x, e0.x) * TBL_INV_SCALE;
    r.y = fmaf(w, e1.y - e0.y, e0.y) * TBL_INV_SCALE;
    return r;
}

__global__ void build_comb_kernel(const float* __restrict__ table)
{
    int j = blockIdx.x * blockDim.x + threadIdx.x;
    if (j >= COMB_N) return;
    int i10 = j >> 1;
    uint4 v;
    v.x = pack_h2(*reinterpret_cast<const float2*>(table + (i10 & HASH_MASK)       * 24 + 20));
    v.y = pack_h2(*reinterpret_cast<const float2*>(table + ((i10 + 1) & HASH_MASK) * 24 + 20));
    v.z = pack_h2(*reinterpret_cast<const float2*>(table + (j & HASH_MASK)         * 24 + 22));
    v.w = pack_h2(*reinterpret_cast<const float2*>(table + ((j + 1) & HASH_MASK)   * 24 + 22));
    g_comb[j] = v;
}

__device__ __forceinline__ void fill_tables(const float* __restrict__ table,
                                            uint2* spair, unsigned* s9)
{
    const int off[10] = {0, 17, 50, 115, 244, 501, 1014, 2039, 4088, 8185};
    for (int e = threadIdx.x; e < SMEM_PAIRS; e += blockDim.x) {
        int l = 0;
        #pragma unroll
        for (int k = 1; k < 9; ++k) l += (e >= off[k]);
        int i = e - off[l];
        uint2 v;
        v.x = pack_h2(*reinterpret_cast<const float2*>(table + i       * 24 + 2 * l));
        v.y = pack_h2(*reinterpret_cast<const float2*>(table + (i + 1) * 24 + 2 * l));
        spair[e] = v;
    }
    for (int i = threadIdx.x; i < L9_ENTRIES; i += blockDim.x)
        s9[i] = pack_h2(*reinterpret_cast<const float2*>(table + i * 24 + 18));
}

__device__ __forceinline__ void compute_point(float xc, const uint2* spair,
                                              const unsigned* s9, uint4 g, float* of)
{
    const int off[10] = {0, 17, 50, 115, 244, 501, 1014, 2039, 4088, 8185};
    float res = 16.0f;
    #pragma unroll
    for (int l = 0; l < 9; ++l) {
        float pos = xc * res;
        int   i0  = __float2int_rd(pos);
        float w   = pos - (float)i0;
        uint2 v   = spair[off[l] + i0];
        float2 r  = lerp_h2pair(v.x, v.y, w);
        of[2 * l]     = r.x;
        of[2 * l + 1] = r.y;
        res *= 2.0f;
    }
    {
        float pos = xc * 8192.0f;
        int   i0  = __float2int_rd(pos);
        float w   = pos - (float)i0;
        float2 r  = lerp_h2pair(s9[i0], s9[i0 + 1], w);
        of[18] = r.x; of[19] = r.y;
    }
    {
        float pos11 = xc * 32768.0f;
        int   i11   = __float2int_rd(pos11);
        float w11   = pos11 - (float)i11;
        int   i10   = i11 >> 1;
        float w10   = pos11 * 0.5f - (float)i10;
        float2 r = lerp_h2pair(g.x, g.y, w10);
        of[20] = r.x; of[21] = r.y;
        r = lerp_h2pair(g.z, g.w, w11);
        of[22] = r.x; of[23] = r.y;
    }
}

// ---------------- TMA kernel ----------------
__global__ void __launch_bounds__(1024, 1)
hashgrid1d_tma_kernel(const float* __restrict__ x,
                      const float* __restrict__ table,
                      float* __restrict__ out, int n,
                      const __grid_constant__ CUtensorMap tmap)
{
    extern __shared__ unsigned char smem_raw[];
    unsigned sbase_s = (unsigned)__cvta_generic_to_shared(smem_raw);
    unsigned pad     = ((sbase_s + 1023u) & ~1023u) - sbase_s;
    unsigned char* stage_g = smem_raw + pad;
    unsigned stage_s = sbase_s + pad;
    uint2*    spair = reinterpret_cast<uint2*>(stage_g + STAGE_BYTES);
    unsigned* s9    = reinterpret_cast<unsigned*>(stage_g + STAGE_BYTES + PAIR_BYTES);

    fill_tables(table, spair, s9);
    __syncthreads();

    const int lane = threadIdx.x & 31;
    const int wid  = threadIdx.x >> 5;
    float4*  my_stage   = reinterpret_cast<float4*>(stage_g + wid * 3072);
    unsigned my_stage_s = stage_s + wid * 3072;

    int gwarp  = (blockIdx.x * blockDim.x + threadIdx.x) >> 5;
    int nwarps = (gridDim.x * blockDim.x) >> 5;
    int step   = nwarps * 32;
    int nfull  = n & ~31;

    for (int b0 = gwarp * 32; b0 < nfull; b0 += step) {
        float xc = fminf(fmaxf(x[b0 + lane], 0.0f), 1.0f);
        uint4 g  = __ldg(&g_comb[__float2int_rd(xc * 32768.0f)]);

        float4 o[6];
        compute_point(xc, spair, s9, g, reinterpret_cast<float*>(o));

        if (lane == 0)
            asm volatile("cp.async.bulk.wait_group.read 0;" ::: "memory");
        __syncwarp();

        // SW128-swizzled conflict-free STS.128
        #pragma unroll
        for (int j = 0; j < 6; ++j) {
            unsigned u = 6u * lane + j;
            unsigned s = u ^ ((u >> 3) & 7u);
            my_stage[s] = o[j];
        }
        __syncwarp();

        if (lane == 0) {
            asm volatile("fence.proxy.async.shared::cta;" ::: "memory");
            int row0 = (b0 >> 5) * 24;
            asm volatile(
                "cp.async.bulk.tensor.2d.global.shared::cta.tile.bulk_group "
                "[%0, {%1, %2}], [%3];"
                :: "l"(&tmap), "r"(0), "r"(row0), "r"(my_stage_s) : "memory");
            asm volatile("cp.async.bulk.commit_group;" ::: "memory");
        }
    }
    asm volatile("cp.async.bulk.wait_group 0;" ::: "memory");

    // tail (n not multiple of 32): guarded direct stores
    for (int b = nfull + gwarp * 32 + lane; b < n; b += step) {
        float xc = fminf(fmaxf(x[b], 0.0f), 1.0f);
        uint4 g  = __ldg(&g_comb[__float2int_rd(xc * 32768.0f)]);
        float4 o[6];
        compute_point(xc, spair, s9, g, reinterpret_cast<float*>(o));
        float4* op = reinterpret_cast<float4*>(out + (size_t)b * 24);
        #pragma unroll
        for (int j = 0; j < 6; ++j) op[j] = o[j];
    }
}

// ---------------- fallback: smem transpose + coalesced STG ----------------
__global__ void __launch_bounds__(1024, 1)
hashgrid1d_fb_kernel(const float* __restrict__ x,
                     const float* __restrict__ table,
                     float* __restrict__ out, int n)
{
    extern __shared__ unsigned char smem_raw[];
    uint2*    spair = reinterpret_cast<uint2*>(smem_raw);
    unsigned* s9    = reinterpret_cast<unsigned*>(smem_raw + PAIR_BYTES);
    float4*   stage = reinterpret_cast<float4*>(smem_raw + TBL_BYTES);

    fill_tables(table, spair, s9);
    __syncthreads();

    const int lane = threadIdx.x & 31;
    float4* my_stage = stage + (threadIdx.x >> 5) * 224;

    int stride = gridDim.x * blockDim.x;
    for (int b = blockIdx.x * blockDim.x + threadIdx.x; b < n; b += stride) {
        float xc = fminf(fmaxf(x[b], 0.0f), 1.0f);
        uint4 g  = __ldg(&g_comb[__float2int_rd(xc * 32768.0f)]);
        float4 o[6];
        compute_point(xc, spair, s9, g, reinterpret_cast<float*>(o));

        #pragma unroll
        for (int j = 0; j < 6; ++j) my_stage[lane * 7 + j] = o[j];
        __syncwarp();
        float4* ob = reinterpret_cast<float4*>(out + (size_t)(b - lane) * 24);
        #pragma unroll
        for (int k = 0; k < 6; ++k) {
            int w4 = lane + 32 * k;
            int p  = (w4 * 2731) >> 14;
            int c  = w4 - p * 6;
            ob[w4] = my_stage[p * 7 + c];
        }
        __syncwarp();
    }
}

extern "C" void kernel_launch(void* const* d_in, const int* in_sizes, int n_in,
                              void* d_out, int out_size)
{
    const float* x     = (const float*)d_in[0];
    const float* table = (const float*)d_in[1];
    float*       out   = (float*)d_out;
    int n = in_sizes[0];
    int nfull = n & ~31;

    int sm_count = 148;
    cudaDeviceGetAttribute(&sm_count, cudaDevAttrMultiProcessorCount, 0);

    bool use_tma = false;
    CUtensorMap tmap;
    void* sym = nullptr;
    cudaDriverEntryPointQueryResult qres;
#if CUDART_VERSION >= 12050
    if (cudaGetDriverEntryPointByVersion("cuTensorMapEncodeTiled", &sym, 12000,
                                         cudaEnableDefault, &qres) != cudaSuccess)
        sym = nullptr;
#else
    if (cudaGetDriverEntryPoint("cuTensorMapEncodeTiled", &sym,
                                cudaEnableDefault, &qres) != cudaSuccess)
        sym = nullptr;
#endif
    if (sym && nfull > 0) {
        typedef CUresult (*Enc)(CUtensorMap*, CUtensorMapDataType, cuuint32_t, void*,
                                const cuuint64_t*, const cuuint64_t*,
                                const cuuint32_t*, const cuuint32_t*,
                                CUtensorMapInterleave, CUtensorMapSwizzle,
                                CUtensorMapL2promotion, CUtensorMapFloatOOBfill);
        Enc enc = (Enc)sym;
        cuuint64_t dims[2]    = {32ull, (cuuint64_t)(nfull / 32) * 24ull};
        cuuint64_t strides[1] = {128ull};
        cuuint32_t box[2]     = {32u, 24u};
        cuuint32_t estr[2]    = {1u, 1u};
        if (enc(&tmap, CU_TENSOR_MAP_DATA_TYPE_FLOAT32, 2, out,
                dims, strides, box, estr,
                CU_TENSOR_MAP_INTERLEAVE_NONE, CU_TENSOR_MAP_SWIZZLE_128B,
                CU_TENSOR_MAP_L2_PROMOTION_L2_128B,
                CU_TENSOR_MAP_FLOAT_OOB_FILL_NONE) == CUDA_SUCCESS)
            use_tma = true;
    }
    if (use_tma &&
        cudaFuncSetAttribute(hashgrid1d_tma_kernel,
                             cudaFuncAttributeMaxDynamicSharedMemorySize,
                             SMEM_TMA) != cudaSuccess)
        use_tma = false;

    build_comb_kernel<<<(COMB_N + 255) / 256, 256>>>(table);

    if (use_tma) {
        hashgrid1d_tma_kernel<<<sm_count, 1024, SMEM_TMA>>>(x, table, out, n, tmap);
    } else {
        cudaFuncSetAttribute(hashgrid1d_fb_kernel,
                             cudaFuncAttributeMaxDynamicSharedMemorySize, SMEM_FB);
        hashgrid1d_fb_kernel<<<sm_count, 1024, SMEM_FB>>>(x, table, out, n);
    }
}

// round 16
// speedup vs baseline: 1.1290x; 1.0004x over previous
#include <cuda_runtime.h>
#include <cuda.h>
#include <cuda_fp16.h>

// HashGrid1D on GB300 — R16 (= R9 memory structure + branchless TMA epilogue).
// R9 verified at 88.6-88.9us. Only change here: the two divergent
// `if (lane==0)` regions per loop iteration (BSSY/BSYNC pairs) are removed:
//  - wait_group.read executed by ALL lanes (empty groups for lanes 1..31),
//  - fence executed uniformly,
//  - TMA issue predicated inside the asm (setp/@p), commit by all lanes.
// Memory structure unchanged: levels 0..8 pair-packed half4 smem (65.5KB),
// level 9 unpaired half2 smem (32.8KB), levels 10+11 fused single L2 gather,
// SW128-swizzled STS.128 staging -> cp.async.bulk.tensor.2d store.

#define HASH_MASK 16383
#define COMB_N    32769
#define SMEM_PAIRS 8185             // sum_{l=0}^{8} ((16<<l)+1)
#define L9_ENTRIES 8194
#define TBL_SCALE     16384.0f
#define TBL_INV_SCALE 6.103515625e-05f  // exact 2^-14
#define PAIR_BYTES  65488           // 8185*8 padded to 16
#define L9_BYTES    32784           // 8194*4 padded to 16
#define TBL_BYTES   (PAIR_BYTES + L9_BYTES)          // 98272
#define STAGE_BYTES (32 * 3072)                       // 98304
#define SMEM_TMA    (1024 + STAGE_BYTES + TBL_BYTES)  // 197600
#define SMEM_FB     (TBL_BYTES + 1024 * 7 * 16)       // 212960

__device__ uint4 g_comb[COMB_N];   // {h2 e10[i10h], h2 e10[i10h+1], h2 e11[i11h], h2 e11[i11h+1]}

__device__ __forceinline__ unsigned pack_h2(float2 a)
{
    __half2 h = __floats2half2_rn(a.x * TBL_SCALE, a.y * TBL_SCALE);
    return *reinterpret_cast<unsigned*>(&h);
}

__device__ __forceinline__ float2 lerp_h2pair(unsigned u0, unsigned u1, float w)
{
    float2 e0 = __half22float2(*reinterpret_cast<__half2*>(&u0));
    float2 e1 = __half22float2(*reinterpret_cast<__half2*>(&u1));
    float2 r;
    r.x = fmaf(w, e1.x - e0.x, e0.x) * TBL_INV_SCALE;
    r.y = fmaf(w, e1.y - e0.y, e0.y) * TBL_INV_SCALE;
    return r;
}

__global__ void build_comb_kernel(const float* __restrict__ table)
{
    int j = blockIdx.x * blockDim.x + threadIdx.x;
    if (j >= COMB_N) return;
    int i10 = j >> 1;
    uint4 v;
    v.x = pack_h2(*reinterpret_cast<const float2*>(table + (i10 & HASH_MASK)       * 24 + 20));
    v.y = pack_h2(*reinterpret_cast<const float2*>(table + ((i10 + 1) & HASH_MASK) * 24 + 20));
    v.z = pack_h2(*reinterpret_cast<const float2*>(table + (j & HASH_MASK)         * 24 + 22));
    v.w = pack_h2(*reinterpret_cast<const float2*>(table + ((j + 1) & HASH_MASK)   * 24 + 22));
    g_comb[j] = v;
}

__device__ __forceinline__ void fill_tables(const float* __restrict__ table,
                                            uint2* spair, unsigned* s9)
{
    const int off[10] = {0, 17, 50, 115, 244, 501, 1014, 2039, 4088, 8185};
    for (int e = threadIdx.x; e < SMEM_PAIRS; e += blockDim.x) {
        int l = 0;
        #pragma unroll
        for (int k = 1; k < 9; ++k) l += (e >= off[k]);
        int i = e - off[l];
        uint2 v;
        v.x = pack_h2(*reinterpret_cast<const float2*>(table + i       * 24 + 2 * l));
        v.y = pack_h2(*reinterpret_cast<const float2*>(table + (i + 1) * 24 + 2 * l));
        spair[e] = v;
    }
    for (int i = threadIdx.x; i < L9_ENTRIES; i += blockDim.x)
        s9[i] = pack_h2(*reinterpret_cast<const float2*>(table + i * 24 + 18));
}

__device__ __forceinline__ void compute_point(float xc, const uint2* spair,
                                              const unsigned* s9, uint4 g, float* of)
{
    const int off[10] = {0, 17, 50, 115, 244, 501, 1014, 2039, 4088, 8185};
    float res = 16.0f;
    #pragma unroll
    for (int l = 0; l < 9; ++l) {
        float pos = xc * res;
        int   i0  = __float2int_rd(pos);
        float w   = pos - (float)i0;
        uint2 v   = spair[off[l] + i0];
        float2 r  = lerp_h2pair(v.x, v.y, w);
        of[2 * l]     = r.x;
        of[2 * l + 1] = r.y;
        res *= 2.0f;
    }
    {
        float pos = xc * 8192.0f;
        int   i0  = __float2int_rd(pos);
        float w   = pos - (float)i0;
        float2 r  = lerp_h2pair(s9[i0], s9[i0 + 1], w);
        of[18] = r.x; of[19] = r.y;
    }
    {
        float pos11 = xc * 32768.0f;
        int   i11   = __float2int_rd(pos11);
        float w11   = pos11 - (float)i11;
        int   i10   = i11 >> 1;
        float w10   = pos11 * 0.5f - (float)i10;
        float2 r = lerp_h2pair(g.x, g.y, w10);
        of[20] = r.x; of[21] = r.y;
        r = lerp_h2pair(g.z, g.w, w11);
        of[22] = r.x; of[23] = r.y;
    }
}

// ---------------- TMA kernel ----------------
__global__ void __launch_bounds__(1024, 1)
hashgrid1d_tma_kernel(const float* __restrict__ x,
                      const float* __restrict__ table,
                      float* __restrict__ out, int n,
                      const __grid_constant__ CUtensorMap tmap)
{
    extern __shared__ unsigned char smem_raw[];
    unsigned sbase_s = (unsigned)__cvta_generic_to_shared(smem_raw);
    unsigned pad     = ((sbase_s + 1023u) & ~1023u) - sbase_s;
    unsigned char* stage_g = smem_raw + pad;
    unsigned stage_s = sbase_s + pad;
    uint2*    spair = reinterpret_cast<uint2*>(stage_g + STAGE_BYTES);
    unsigned* s9    = reinterpret_cast<unsigned*>(stage_g + STAGE_BYTES + PAIR_BYTES);

    fill_tables(table, spair, s9);
    __syncthreads();

    const int lane = threadIdx.x & 31;
    const int wid  = threadIdx.x >> 5;
    float4*  my_stage   = reinterpret_cast<float4*>(stage_g + wid * 3072);
    unsigned my_stage_s = stage_s + wid * 3072;
    const unsigned is_lane0 = (lane == 0) ? 1u : 0u;

    int gwarp  = (blockIdx.x * blockDim.x + threadIdx.x) >> 5;
    int nwarps = (gridDim.x * blockDim.x) >> 5;
    int step   = nwarps * 32;
    int nfull  = n & ~31;

    for (int b0 = gwarp * 32; b0 < nfull; b0 += step) {
        float xc = fminf(fmaxf(x[b0 + lane], 0.0f), 1.0f);
        uint4 g  = __ldg(&g_comb[__float2int_rd(xc * 32768.0f)]);

        float4 o[6];
        compute_point(xc, spair, s9, g, reinterpret_cast<float*>(o));

        // All-lane wait: lanes 1..31 hold only empty groups -> immediate.
        // The syncwarp below makes lane 0's real wait order all lanes' STS.
        asm volatile("cp.async.bulk.wait_group.read 0;" ::: "memory");
        __syncwarp();

        // SW128-swizzled conflict-free STS.128
        #pragma unroll
        for (int j = 0; j < 6; ++j) {
            unsigned u = 6u * lane + j;
            unsigned s = u ^ ((u >> 3) & 7u);
            my_stage[s] = o[j];
        }
        __syncwarp();

        // Uniform fence + predicated single-thread TMA issue (no BSSY/BSYNC).
        asm volatile("fence.proxy.async.shared::cta;" ::: "memory");
        {
            int row0 = (b0 >> 5) * 24;
            asm volatile(
                "{\n\t"
                ".reg .pred p;\n\t"
                "setp.ne.u32 p, %0, 0;\n\t"
                "@p cp.async.bulk.tensor.2d.global.shared::cta.tile.bulk_group "
                "[%1, {%2, %3}], [%4];\n\t"
                "}"
                :: "r"(is_lane0), "l"(&tmap), "r"(0), "r"(row0), "r"(my_stage_s)
                : "memory");
            asm volatile("cp.async.bulk.commit_group;" ::: "memory");
        }
    }
    asm volatile("cp.async.bulk.wait_group 0;" ::: "memory");

    // tail (n not multiple of 32): guarded direct stores
    for (int b = nfull + gwarp * 32 + lane; b < n; b += step) {
        float xc = fminf(fmaxf(x[b], 0.0f), 1.0f);
        uint4 g  = __ldg(&g_comb[__float2int_rd(xc * 32768.0f)]);
        float4 o[6];
        compute_point(xc, spair, s9, g, reinterpret_cast<float*>(o));
        float4* op = reinterpret_cast<float4*>(out + (size_t)b * 24);
        #pragma unroll
        for (int j = 0; j < 6; ++j) op[j] = o[j];
    }
}

// ---------------- fallback: smem transpose + coalesced STG ----------------
__global__ void __launch_bounds__(1024, 1)
hashgrid1d_fb_kernel(const float* __restrict__ x,
                     const float* __restrict__ table,
                     float* __restrict__ out, int n)
{
    extern __shared__ unsigned char smem_raw[];
    uint2*    spair = reinterpret_cast<uint2*>(smem_raw);
    unsigned* s9    = reinterpret_cast<unsigned*>(smem_raw + PAIR_BYTES);
    float4*   stage = reinterpret_cast<float4*>(smem_raw + TBL_BYTES);

    fill_tables(table, spair, s9);
    __syncthreads();

    const int lane = threadIdx.x & 31;
    float4* my_stage = stage + (threadIdx.x >> 5) * 224;

    int stride = gridDim.x * blockDim.x;
    for (int b = blockIdx.x * blockDim.x + threadIdx.x; b < n; b += stride) {
        float xc = fminf(fmaxf(x[b], 0.0f), 1.0f);
        uint4 g  = __ldg(&g_comb[__float2int_rd(xc * 32768.0f)]);
        float4 o[6];
        compute_point(xc, spair, s9, g, reinterpret_cast<float*>(o));

        #pragma unroll
        for (int j = 0; j < 6; ++j) my_stage[lane * 7 + j] = o[j];
        __syncwarp();
        float4* ob = reinterpret_cast<float4*>(out + (size_t)(b - lane) * 24);
        #pragma unroll
        for (int k = 0; k < 6; ++k) {
            int w4 = lane + 32 * k;
            int p  = (w4 * 2731) >> 14;
            int c  = w4 - p * 6;
            ob[w4] = my_stage[p * 7 + c];
        }
        __syncwarp();
    }
}

extern "C" void kernel_launch(void* const* d_in, const int* in_sizes, int n_in,
                              void* d_out, int out_size)
{
    const float* x     = (const float*)d_in[0];
    const float* table = (const float*)d_in[1];
    float*       out   = (float*)d_out;
    int n = in_sizes[0];
    int nfull = n & ~31;

    int sm_count = 148;
    cudaDeviceGetAttribute(&sm_count, cudaDevAttrMultiProcessorCount, 0);

    bool use_tma = false;
    CUtensorMap tmap;
    void* sym = nullptr;
    cudaDriverEntryPointQueryResult qres;
#if CUDART_VERSION >= 12050
    if (cudaGetDriverEntryPointByVersion("cuTensorMapEncodeTiled", &sym, 12000,
                                         cudaEnableDefault, &qres) != cudaSuccess)
        sym = nullptr;
#else
    if (cudaGetDriverEntryPoint("cuTensorMapEncodeTiled", &sym,
                                cudaEnableDefault, &qres) != cudaSuccess)
        sym = nullptr;
#endif
    if (sym && nfull > 0) {
        typedef CUresult (*Enc)(CUtensorMap*, CUtensorMapDataType, cuuint32_t, void*,
                                const cuuint64_t*, const cuuint64_t*,
                                const cuuint32_t*, const cuuint32_t*,
                                CUtensorMapInterleave, CUtensorMapSwizzle,
                                CUtensorMapL2promotion, CUtensorMapFloatOOBfill);
        Enc enc = (Enc)sym;
        cuuint64_t dims[2]    = {32ull, (cuuint64_t)(nfull / 32) * 24ull};
        cuuint64_t strides[1] = {128ull};
        cuuint32_t box[2]     = {32u, 24u};
        cuuint32_t estr[2]    = {1u, 1u};
        if (enc(&tmap, CU_TENSOR_MAP_DATA_TYPE_FLOAT32, 2, out,
                dims, strides, box, estr,
                CU_TENSOR_MAP_INTERLEAVE_NONE, CU_TENSOR_MAP_SWIZZLE_128B,
                CU_TENSOR_MAP_L2_PROMOTION_L2_128B,
                CU_TENSOR_MAP_FLOAT_OOB_FILL_NONE) == CUDA_SUCCESS)
            use_tma = true;
    }
    if (use_tma &&
        cudaFuncSetAttribute(hashgrid1d_tma_kernel,
                             cudaFuncAttributeMaxDynamicSharedMemorySize,
                             SMEM_TMA) != cudaSuccess)
        use_tma = false;

    build_comb_kernel<<<(COMB_N + 255) / 256, 256>>>(table);

    if (use_tma) {
        hashgrid1d_tma_kernel<<<sm_count, 1024, SMEM_TMA>>>(x, table, out, n, tmap);
    } else {
        cudaFuncSetAttribute(hashgrid1d_fb_kernel,
                             cudaFuncAttributeMaxDynamicSharedMemorySize, SMEM_FB);
        hashgrid1d_fb_kernel<<<sm_count, 1024, SMEM_FB>>>(x, table, out, n);
    }
}